// round 11
// baseline (speedup 1.0000x reference)
#include <cuda_runtime.h>
#include <math.h>
#include <stdint.h>

#define BB     2
#define NN     1024
#define DIMC   512
#define NHEADS 8
#define DHH    64
#define INNERC 512
#define FFC    2048
#define NDEPTH 2
#define MM     (BB*NN)
#define EPSF   1e-6f
#define ATT_SCALE 0.125f

// ---------------- scratch ----------------
__device__ float2 g_x [MM*DIMC];
__device__ float2 g_hn[MM*DIMC];
__device__ float2 g_q [MM*INNERC];
__device__ float2 g_kv[MM*2*INNERC];
__device__ float2 g_o [MM*INNERC];
__device__ float2 g_ff[MM*FFC];
__device__ float2 g_rope[NN*DHH];
__device__ float2 g_wtf[6291456];     // tf32-rounded weights (all layers)

// complex-element offsets into g_wtf
#define OFF_QKV 0                     // [l][512][1536]  (Wq | Wkv concat)
#define OFF_WO  1572864
#define OFF_W1  2097152
#define OFF_W2  4194304

__device__ __forceinline__ float2 cmulf(float2 a, float2 b) {
    return make_float2(a.x*b.x - a.y*b.y, a.x*b.y + a.y*b.x);
}
__device__ __forceinline__ uint32_t f2tf32(float x) {
    uint32_t u;
    asm("cvt.rna.tf32.f32 %0, %1;" : "=r"(u) : "f"(x));
    return u;
}
__device__ __forceinline__ float tf32f(float x) {
    return __uint_as_float(f2tf32(x));
}
__device__ __forceinline__ void mma_tf32(float* d, const uint32_t* a, const uint32_t* b) {
    asm volatile(
        "mma.sync.aligned.m16n8k8.row.col.f32.tf32.tf32.f32 "
        "{%0,%1,%2,%3},{%4,%5,%6,%7},{%8,%9},{%0,%1,%2,%3};"
        : "+f"(d[0]), "+f"(d[1]), "+f"(d[2]), "+f"(d[3])
        : "r"(a[0]), "r"(a[1]), "r"(a[2]), "r"(a[3]), "r"(b[0]), "r"(b[1]));
}
__device__ __forceinline__ void cp16(uint32_t dst, const void* src) {
    asm volatile("cp.async.cg.shared.global [%0], [%1], 16;" :: "r"(dst), "l"(src));
}
__device__ __forceinline__ void cp_commit() { asm volatile("cp.async.commit_group;"); }
template<int N> __device__ __forceinline__ void cp_wait() {
    asm volatile("cp.async.wait_group %0;" :: "n"(N));
}

// ---------------- weight pre-rounding ----------------
__global__ __launch_bounds__(256) void ct_round_copy(const float4* __restrict__ src,
                                                     float4* __restrict__ dst, int n4) {
    int i = blockIdx.x*blockDim.x + threadIdx.x;
    if (i >= n4) return;
    float4 f = src[i];
    dst[i] = make_float4(tf32f(f.x), tf32f(f.y), tf32f(f.z), tf32f(f.w));
}

// concat Wq|Wkv -> [l][512][1536], rounded. n4 indexes float4 (=2 complex).
__global__ __launch_bounds__(256) void ct_concat_qkv(const float4* __restrict__ wq,
                                                     const float4* __restrict__ wkv,
                                                     float4* __restrict__ dst) {
    int i = blockIdx.x*blockDim.x + threadIdx.x;
    const int n4tot = NDEPTH*DIMC*1536/2;
    if (i >= n4tot) return;
    int l   = i / (DIMC*768);
    int rem = i % (DIMC*768);
    int k   = rem / 768;
    int n4  = rem % 768;
    float4 f;
    if (n4 < 256) f = wq [l*131072 + k*256 + n4];
    else          f = wkv[l*262144 + k*512 + (n4 - 256)];
    dst[i] = make_float4(tf32f(f.x), tf32f(f.y), tf32f(f.z), tf32f(f.w));
}

// ---------------- rope table ----------------
__global__ void ct_rope_init() {
    int i = blockIdx.x*blockDim.x + threadIdx.x;
    if (i >= NN*DHH) return;
    int n = i / DHH, d = i % DHH;
    double inv = exp(-((double)d / (double)DHH) * log(10000.0));
    double fr  = (double)n * inv;
    g_rope[i] = make_float2((float)cos(fr), (float)sin(fr));
}

// ---------------- complex rmsnorm (optionally tf32-rounds output) ------------
__global__ __launch_bounds__(128) void ct_rmsnorm(const float2* __restrict__ in,
                                                  const float2* __restrict__ gamma,
                                                  float2* __restrict__ out, int rnd) {
    int row = blockIdx.x;
    const float2* xr = in + row*DIMC;
    float ss = 0.f;
    for (int d = threadIdx.x; d < DIMC; d += 128) {
        float2 v = xr[d];
        ss = fmaf(v.x, v.x, ss);
        ss = fmaf(v.y, v.y, ss);
    }
#pragma unroll
    for (int off = 16; off; off >>= 1) ss += __shfl_xor_sync(0xffffffffu, ss, off);
    __shared__ float sred[4];
    if ((threadIdx.x & 31) == 0) sred[threadIdx.x >> 5] = ss;
    __syncthreads();
    ss = sred[0] + sred[1] + sred[2] + sred[3];
    float sc = rsqrtf(ss * (1.f/(float)DIMC) + EPSF);
    for (int d = threadIdx.x; d < DIMC; d += 128) {
        float2 v = xr[d];
        float2 g = gamma[d];
        float re = sc*(v.x*g.x - v.y*g.y);
        float im = sc*(v.x*g.y + v.y*g.x);
        if (rnd) { re = tf32f(re); im = tf32f(im); }
        out[row*DIMC + d] = make_float2(re, im);
    }
}

// ---------------- cp.async 3-stage tf32 complex GEMM -------------------------
#define TBM 128
#define TBN 64
#define TBK 16
#define KAPAD 20
#define CG_STAGE 29184   // A: 128*20*8 = 20480  +  B: 16*68*8 = 8704
#define CG_SMEM  (3*CG_STAGE)

// epi: 2=residual 3=FF1 4=FF2+res 5=fused QKV (writes g_q/g_kv)
__device__ __forceinline__ void epilog(float2* __restrict__ C, int NC, int m, int n,
                                       float re, float im, int epi,
                                       const float2* __restrict__ bias,
                                       const float* __restrict__ modb) {
    float2 r = make_float2(re, im);
    if (epi == 5) {
        if (n < INNERC) {               // Q
            float2 ph = g_rope[(m & (NN-1))*DHH + (n & (DHH-1))];
            float2 t = cmulf(r, ph);
            g_q[(size_t)m*INNERC + n] = make_float2(tf32f(t.x), tf32f(t.y));
        } else if (n < 2*INNERC) {      // K (roped)
            int kk = n - INNERC;
            float2 ph = g_rope[(m & (NN-1))*DHH + (kk & (DHH-1))];
            float2 t = cmulf(r, ph);
            g_kv[(size_t)m*2*INNERC + kk] = make_float2(tf32f(t.x), tf32f(t.y));
        } else {                        // V
            int vv = n - 2*INNERC;
            g_kv[(size_t)m*2*INNERC + INNERC + vv] = make_float2(tf32f(r.x), tf32f(r.y));
        }
        return;
    }
    int idx = m*NC + n;
    if (epi == 2) {
        float2 c = C[idx];
        C[idx] = make_float2(c.x + r.x, c.y + r.y);       // residual: full fp32
    } else if (epi == 3) {
        float2 bv = bias[n];
        r.x += bv.x; r.y += bv.y;
        float mag = sqrtf(r.x*r.x + r.y*r.y);
        float t = fmaxf(mag + *modb, 0.f);
        float cl = t*t;
        if (mag > 0.f) {
            float s = cl / mag;
            r.x *= s; r.y *= s;
        } else {
            r.x = cl; r.y = 0.f;
        }
        C[idx] = make_float2(tf32f(r.x), tf32f(r.y));     // FF1: W2 GEMM input
    } else {  // 4
        float2 bv = bias[n];
        float2 c = C[idx];
        C[idx] = make_float2(c.x + r.x + bv.x, c.y + r.y + bv.y);  // residual
    }
}

__global__ __launch_bounds__(256, 2) void ct_cgemm_tc(const float2* __restrict__ A,
                                                      const float2* __restrict__ W,
                                                      float2* __restrict__ C,
                                                      int K, int NC, int epi,
                                                      const float2* __restrict__ bias,
                                                      const float* __restrict__ modb) {
    extern __shared__ char dynsm[];
    int tid  = threadIdx.x;
    int warp = tid >> 5;
    int lane = tid & 31;
    int g    = lane >> 2;
    int tg   = lane & 3;
    int warp_m = warp & 3;
    int warp_n = warp >> 2;
    int m0 = blockIdx.y * TBM;
    int n0 = blockIdx.x * TBN;

    uint32_t smbase = (uint32_t)__cvta_generic_to_shared(dynsm);

    float cr[2][4][4] = {};
    float ci[2][4][4] = {};

    const int ntiles = K / TBK;

    auto stageLoad = [&](int s, int k0) {
        uint32_t ab = smbase + s*CG_STAGE;
#pragma unroll
        for (int i = 0; i < 4; i++) {
            int e = tid + i*256;
            int r = e >> 3, c4 = e & 7;
            cp16(ab + (uint32_t)(r*KAPAD + c4*2)*8, &A[(size_t)(m0 + r)*K + k0 + c4*2]);
        }
        uint32_t bb = ab + 20480;
#pragma unroll
        for (int i = 0; i < 2; i++) {
            int e = tid + i*256;
            int r = e >> 5, c4 = e & 31;
            cp16(bb + (uint32_t)(r*68 + c4*2)*8, &W[(size_t)(k0 + r)*NC + n0 + c4*2]);
        }
        cp_commit();
    };

    stageLoad(0, 0);
    if (ntiles > 1) stageLoad(1, TBK);
    for (int kt = 0; kt < ntiles; kt++) {
        if      (kt + 2 < ntiles) { stageLoad((kt+2)%3, (kt+2)*TBK); cp_wait<2>(); }
        else if (kt + 1 < ntiles) { cp_wait<1>(); }
        else                      { cp_wait<0>(); }
        __syncthreads();

        const float2* As_ = reinterpret_cast<const float2*>(dynsm + (kt%3)*CG_STAGE);
        const float2* Bs_ = reinterpret_cast<const float2*>(dynsm + (kt%3)*CG_STAGE + 20480);

#pragma unroll
        for (int ks = 0; ks < TBK; ks += 8) {
            uint32_t ar[2][4], ai[2][4], nai[2][4];
            uint32_t br[4][2], bi[4][2];
#pragma unroll
            for (int mt = 0; mt < 2; mt++) {
                int mb = warp_m*32 + mt*16;
                float2 q0 = As_[(mb + g    )*KAPAD + ks + tg    ];
                float2 q1 = As_[(mb + g + 8)*KAPAD + ks + tg    ];
                float2 q2 = As_[(mb + g    )*KAPAD + ks + tg + 4];
                float2 q3 = As_[(mb + g + 8)*KAPAD + ks + tg + 4];
                ar[mt][0] = __float_as_uint(q0.x); ai[mt][0] = __float_as_uint(q0.y);
                ar[mt][1] = __float_as_uint(q1.x); ai[mt][1] = __float_as_uint(q1.y);
                ar[mt][2] = __float_as_uint(q2.x); ai[mt][2] = __float_as_uint(q2.y);
                ar[mt][3] = __float_as_uint(q3.x); ai[mt][3] = __float_as_uint(q3.y);
#pragma unroll
                for (int t = 0; t < 4; t++) nai[mt][t] = ai[mt][t] ^ 0x80000000u;
            }
#pragma unroll
            for (int nt = 0; nt < 4; nt++) {
                int nb = warp_n*32 + nt*8;
                float2 w0 = Bs_[(ks + tg    )*68 + nb + g];
                float2 w1 = Bs_[(ks + tg + 4)*68 + nb + g];
                br[nt][0] = __float_as_uint(w0.x); bi[nt][0] = __float_as_uint(w0.y);
                br[nt][1] = __float_as_uint(w1.x); bi[nt][1] = __float_as_uint(w1.y);
            }
#pragma unroll
            for (int mt = 0; mt < 2; mt++)
#pragma unroll
                for (int nt = 0; nt < 4; nt++) {
                    mma_tf32(cr[mt][nt], ar[mt],  br[nt]);
                    mma_tf32(cr[mt][nt], nai[mt], bi[nt]);
                    mma_tf32(ci[mt][nt], ar[mt],  bi[nt]);
                    mma_tf32(ci[mt][nt], ai[mt],  br[nt]);
                }
        }
        __syncthreads();
    }

#pragma unroll
    for (int mt = 0; mt < 2; mt++)
#pragma unroll
        for (int nt = 0; nt < 4; nt++)
#pragma unroll
            for (int c = 0; c < 4; c++) {
                int row = m0 + warp_m*32 + mt*16 + g + ((c >= 2) ? 8 : 0);
                int col = n0 + warp_n*32 + nt*8 + 2*tg + (c & 1);
                epilog(C, NC, row, col, cr[mt][nt][c], ci[mt][nt][c], epi, bias, modb);
            }
}

// ---------------- merged-variant attention (cp.async K/V double buffer) -----
#define AQ2 32
#define AK2 16
#define KVP 68
#define PST 20
#define AT_KV_STAGE 17408
#define AT_Q_OFF    (2*AT_KV_STAGE)
#define AT_SMEM     (AT_Q_OFF + 32*KVP*8)

__global__ __launch_bounds__(256, 2) void ct_attention_tc4() {
    extern __shared__ char asmem[];
    float2 (*Qc)[KVP] = reinterpret_cast<float2(*)[KVP]>(asmem + AT_Q_OFF);
    float* Pbase  = reinterpret_cast<float*>(asmem + AT_Q_OFF);
    float* planes = reinterpret_cast<float*>(asmem);

    int bh = blockIdx.x;
    int b  = bh >> 3;
    int h  = bh & 7;
    int q0 = blockIdx.y * AQ2;
    int tid = threadIdx.x, warp = tid >> 5, lane = tid & 31;
    int g = lane >> 2, tg = lane & 3;
    int v  = warp & 3;
    int qh = warp >> 2;
    int m0 = qh * 16;
    float* Ps = Pbase + warp * (16 * PST);

    uint32_t smbase = (uint32_t)__cvta_generic_to_shared(asmem);

#pragma unroll
    for (int i = 0; i < 4; i++) {
        int e = tid + i*256;
        int row = e >> 5, c4 = e & 31;
        *reinterpret_cast<float4*>(&Qc[row][c4*2]) =
            *reinterpret_cast<const float4*>(
                &g_q[(size_t)(b*NN + q0 + row)*INNERC + h*DHH + c4*2]);
    }
    __syncthreads();

    uint32_t qa[8][4];
#pragma unroll
    for (int ks = 0; ks < 8; ks++) {
        float2 c0 = Qc[m0 + g    ][ks*8 + tg];
        float2 c1 = Qc[m0 + g + 8][ks*8 + tg];
        float2 c2 = Qc[m0 + g    ][ks*8 + tg + 4];
        float2 c3 = Qc[m0 + g + 8][ks*8 + tg + 4];
        qa[ks][0] = __float_as_uint((v < 2) ? c0.x : c0.y);
        qa[ks][1] = __float_as_uint((v < 2) ? c1.x : c1.y);
        qa[ks][2] = __float_as_uint((v < 2) ? c2.x : c2.y);
        qa[ks][3] = __float_as_uint((v < 2) ? c3.x : c3.y);
    }

    auto loadKV = [&](int s, int kt) {
        uint32_t base = smbase + s*AT_KV_STAGE;
#pragma unroll
        for (int i = 0; i < 2; i++) {
            int e = tid + i*256;
            int row = e >> 5, c4 = e & 31;
            const float2* src = &g_kv[(size_t)(b*NN + kt + row)*2*INNERC + h*DHH + c4*2];
            cp16(base + (uint32_t)(row*KVP + c4*2)*8, src);
            cp16(base + 8704 + (uint32_t)(row*KVP + c4*2)*8, src + INNERC);
        }
        cp_commit();
    };

    float o[8][4] = {};
    float lsum_lo = 0.f, lsum_hi = 0.f;
    const int ntiles = NN / AK2;

    loadKV(0, 0);
    for (int t = 0; t < ntiles; t++) {
        if (t + 1 < ntiles) { loadKV((t+1)&1, (t+1)*AK2); cp_wait<1>(); }
        else                { cp_wait<0>(); }
        __syncthreads();

        const float2 (*Kc)[KVP] = reinterpret_cast<const float2(*)[KVP]>(asmem + (t&1)*AT_KV_STAGE);
        const float2 (*Vc)[KVP] = reinterpret_cast<const float2(*)[KVP]>(asmem + (t&1)*AT_KV_STAGE + 8704);

        float sacc[2][4] = {};
#pragma unroll
        for (int ks = 0; ks < 8; ks++) {
#pragma unroll
            for (int nt = 0; nt < 2; nt++) {
                float2 k0 = Kc[nt*8 + g][ks*8 + tg];
                float2 k1 = Kc[nt*8 + g][ks*8 + tg + 4];
                uint32_t bb[2];
                bb[0] = __float_as_uint((v & 1) ? -k0.y : k0.x);
                bb[1] = __float_as_uint((v & 1) ? -k1.y : k1.x);
                mma_tf32(sacc[nt], qa[ks], bb);
            }
        }

#pragma unroll
        for (int nt = 0; nt < 2; nt++) {
            float p0 = tf32f(__expf(sacc[nt][0] * ATT_SCALE));
            float p1 = tf32f(__expf(sacc[nt][1] * ATT_SCALE));
            float p2 = tf32f(__expf(sacc[nt][2] * ATT_SCALE));
            float p3 = tf32f(__expf(sacc[nt][3] * ATT_SCALE));
            lsum_lo += p0 + p1;
            lsum_hi += p2 + p3;
            *reinterpret_cast<float2*>(&Ps[(g    )*PST + nt*8 + 2*tg]) = make_float2(p0, p1);
            *reinterpret_cast<float2*>(&Ps[(g + 8)*PST + nt*8 + 2*tg]) = make_float2(p2, p3);
        }
        __syncwarp();

#pragma unroll
        for (int k8 = 0; k8 < AK2; k8 += 8) {
            uint32_t pa[4];
            pa[0] = __float_as_uint(Ps[(g    )*PST + k8 + tg    ]);
            pa[1] = __float_as_uint(Ps[(g + 8)*PST + k8 + tg    ]);
            pa[2] = __float_as_uint(Ps[(g    )*PST + k8 + tg + 4]);
            pa[3] = __float_as_uint(Ps[(g + 8)*PST + k8 + tg + 4]);
#pragma unroll
            for (int nt = 0; nt < 8; nt++) {
                float2 v0 = Vc[k8 + tg    ][nt*8 + g];
                float2 v1 = Vc[k8 + tg + 4][nt*8 + g];
                uint32_t bb[2];
                bb[0] = __float_as_uint((v < 2) ? v0.x : v0.y);
                bb[1] = __float_as_uint((v < 2) ? v1.x : v1.y);
                mma_tf32(o[nt], pa, bb);
            }
        }
        __syncthreads();
    }

#pragma unroll
    for (int off = 1; off <= 2; off <<= 1) {
        lsum_lo += __shfl_xor_sync(0xffffffffu, lsum_lo, off);
        lsum_hi += __shfl_xor_sync(0xffffffffu, lsum_hi, off);
    }
    float inv_lo = 1.f / lsum_lo;
    float inv_hi = 1.f / lsum_hi;
    float* pl = planes + v * (AQ2 * DHH);
#pragma unroll
    for (int nt = 0; nt < 8; nt++) {
        int col = nt*8 + 2*tg;
        pl[(m0 + g    )*DHH + col    ] = o[nt][0] * inv_lo;
        pl[(m0 + g    )*DHH + col + 1] = o[nt][1] * inv_lo;
        pl[(m0 + g + 8)*DHH + col    ] = o[nt][2] * inv_hi;
        pl[(m0 + g + 8)*DHH + col + 1] = o[nt][3] * inv_hi;
    }
    __syncthreads();

#pragma unroll
    for (int i = 0; i < 8; i++) {
        int e = tid + i*256;
        int row = e >> 6, d = e & 63;
        float re = planes[             row*DHH + d] - planes[3*AQ2*DHH + row*DHH + d];
        float im = planes[  AQ2*DHH + row*DHH + d] + planes[2*AQ2*DHH + row*DHH + d];
        g_o[(size_t)(b*NN + q0 + row)*INNERC + h*DHH + d] =
            make_float2(tf32f(re), tf32f(im));
    }
}

// ---------------- launcher ----------------
extern "C" void kernel_launch(void* const* d_in, const int* in_sizes, int n_in,
                              void* d_out, int out_size) {
    (void)in_sizes; (void)n_in; (void)out_size;
    const float2* x          = (const float2*)d_in[0];
    const float2* gamma_attn = (const float2*)d_in[1];
    const float2* Wq         = (const float2*)d_in[2];
    const float2* Wkv        = (const float2*)d_in[3];
    const float2* Wo         = (const float2*)d_in[4];
    const float2* gamma_ff   = (const float2*)d_in[5];
    const float2* W1         = (const float2*)d_in[6];
    const float2* b1         = (const float2*)d_in[7];
    const float*  modb       = (const float*)d_in[8];
    const float2* W2         = (const float2*)d_in[9];
    const float2* b2         = (const float2*)d_in[10];
    const float2* gfin       = (const float2*)d_in[11];

    float2 *px, *phn, *pq, *pkv, *po, *pff, *pw;
    cudaGetSymbolAddress((void**)&px,  g_x);
    cudaGetSymbolAddress((void**)&phn, g_hn);
    cudaGetSymbolAddress((void**)&pq,  g_q);
    cudaGetSymbolAddress((void**)&pkv, g_kv);
    cudaGetSymbolAddress((void**)&po,  g_o);
    cudaGetSymbolAddress((void**)&pff, g_ff);
    cudaGetSymbolAddress((void**)&pw,  g_wtf);

    cudaFuncSetAttribute(ct_cgemm_tc, cudaFuncAttributeMaxDynamicSharedMemorySize, CG_SMEM);
    cudaFuncSetAttribute(ct_attention_tc4, cudaFuncAttributeMaxDynamicSharedMemorySize, AT_SMEM);

    cudaMemcpyAsync(px, x, sizeof(float2)*MM*DIMC, cudaMemcpyDeviceToDevice);
    ct_rope_init<<<(NN*DHH + 255)/256, 256>>>();

    // pre-round weights: fused QKV concat + the rest
    ct_concat_qkv<<<(NDEPTH*DIMC*1536/2 + 255)/256, 256>>>(
        (const float4*)Wq, (const float4*)Wkv, (float4*)(pw + OFF_QKV));
    struct { const float2* s; size_t off; int n4; } wcp[3] = {
        {Wo,  OFF_WO, NDEPTH*INNERC*DIMC/2},
        {W1,  OFF_W1, NDEPTH*DIMC*FFC/2},
        {W2,  OFF_W2, NDEPTH*FFC*DIMC/2},
    };
    for (int i = 0; i < 3; i++)
        ct_round_copy<<<(wcp[i].n4 + 255)/256, 256>>>(
            (const float4*)wcp[i].s, (float4*)(pw + wcp[i].off), wcp[i].n4);

    for (int l = 0; l < NDEPTH; l++) {
        ct_rmsnorm<<<MM, 128>>>(px, gamma_attn + l*DIMC, phn, 1);
        ct_cgemm_tc<<<dim3(1536/TBN, MM/TBM), 256, CG_SMEM>>>(
            phn, pw + OFF_QKV + (size_t)l*DIMC*1536, nullptr, DIMC, 1536, 5, nullptr, nullptr);
        ct_attention_tc4<<<dim3(BB*NHEADS, NN/AQ2), 256, AT_SMEM>>>();
        ct_cgemm_tc<<<dim3(DIMC/TBN, MM/TBM), 256, CG_SMEM>>>(
            po, pw + OFF_WO + (size_t)l*INNERC*DIMC, px, INNERC, DIMC, 2, nullptr, nullptr);
        ct_rmsnorm<<<MM, 128>>>(px, gamma_ff + l*DIMC, phn, 1);
        ct_cgemm_tc<<<dim3(FFC/TBN,  MM/TBM), 256, CG_SMEM>>>(
            phn, pw + OFF_W1 + (size_t)l*DIMC*FFC, pff, DIMC, FFC, 3, b1 + l*FFC,  modb + l);
        ct_cgemm_tc<<<dim3(DIMC/TBN, MM/TBM), 256, CG_SMEM>>>(
            pff, pw + OFF_W2 + (size_t)l*FFC*DIMC, px,  FFC,  DIMC, 4, b2 + l*DIMC, nullptr);
    }
    ct_rmsnorm<<<MM, 128>>>(px, gfin, (float2*)d_out, 0);
}

// round 13
// speedup vs baseline: 1.8064x; 1.8064x over previous
#include <cuda_runtime.h>
#include <cuda_fp16.h>
#include <math.h>
#include <stdint.h>

#define BB     2
#define NN     1024
#define DIMC   512
#define NHEADS 8
#define DHH    64
#define INNERC 512
#define FFC    2048
#define NDEPTH 2
#define MM     (BB*NN)
#define EPSF   1e-6f
#define ATT_SCALE 0.125f

// ---------------- scratch ----------------
__device__ float2 g_x [MM*DIMC];          // residual (fp32)
__device__ float2 g_rope[NN*DHH];
__device__ __half g_hre[MM*DIMC],   g_him[MM*DIMC];    // rmsnorm out
__device__ __half g_qre[MM*INNERC], g_qim[MM*INNERC];  // Q (roped)
__device__ __half g_kre[MM*INNERC], g_kim[MM*INNERC];  // K (roped)
__device__ __half g_vtre[MM*INNERC], g_vtim[MM*INNERC];// V transposed [bh][d][tok]
__device__ __half g_ore[MM*INNERC], g_oim[MM*INNERC];  // attention out
__device__ __half g_fre[MM*FFC],    g_fim[MM*FFC];     // FF intermediate
__device__ __half g_wh[12582912];                      // all weights, [n][k] re|im planes

// half-element offsets into g_wh (per matrix; per-layer stride = 2*N*K)
#define WQ_OFF  0u
#define WKV_OFF 1048576u
#define WO_OFF  3145728u
#define W1_OFF  4194304u
#define W2_OFF  8388608u

__device__ __forceinline__ void mma_f16(float* d, const uint32_t* a, const uint32_t* b) {
    asm volatile(
        "mma.sync.aligned.m16n8k16.row.col.f32.f16.f16.f32 "
        "{%0,%1,%2,%3},{%4,%5,%6,%7},{%8,%9},{%0,%1,%2,%3};"
        : "+f"(d[0]), "+f"(d[1]), "+f"(d[2]), "+f"(d[3])
        : "r"(a[0]), "r"(a[1]), "r"(a[2]), "r"(a[3]), "r"(b[0]), "r"(b[1]));
}
__device__ __forceinline__ void cp16(uint32_t dst, const void* src) {
    asm volatile("cp.async.cg.shared.global [%0], [%1], 16;" :: "r"(dst), "l"(src));
}
__device__ __forceinline__ void cp_commit() { asm volatile("cp.async.commit_group;"); }
template<int N> __device__ __forceinline__ void cp_wait() {
    asm volatile("cp.async.wait_group %0;" :: "n"(N));
}

// ---------------- weight prep: transpose + fp16 convert ----------------
// src: [l][K][N] complex fp32 -> dst: [l][ re[N][K] | im[N][K] ] half
__global__ __launch_bounds__(256) void ct_wprep(const float2* __restrict__ src,
                                                __half* __restrict__ dst, int K, int N) {
    int l = blockIdx.z;
    src += (size_t)l*K*N;
    dst += (size_t)l*2*N*K;
    __shared__ float2 tile[32][33];
    int n0 = blockIdx.x*32, k0 = blockIdx.y*32;
    int tx = threadIdx.x & 31, ty = threadIdx.x >> 5;
    for (int i = ty; i < 32; i += 8)
        tile[i][tx] = src[(size_t)(k0+i)*N + n0 + tx];
    __syncthreads();
    for (int i = ty; i < 32; i += 8) {
        float2 v = tile[tx][i];
        size_t o = (size_t)(n0+i)*K + k0 + tx;
        dst[o] = __float2half(v.x);
        dst[(size_t)N*K + o] = __float2half(v.y);
    }
}

// ---------------- rope table ----------------
__global__ void ct_rope_init() {
    int i = blockIdx.x*blockDim.x + threadIdx.x;
    if (i >= NN*DHH) return;
    int n = i / DHH, d = i % DHH;
    double inv = exp(-((double)d / (double)DHH) * log(10000.0));
    double fr  = (double)n * inv;
    g_rope[i] = make_float2((float)cos(fr), (float)sin(fr));
}

// ---------------- complex rmsnorm -> half planes ----------------
__global__ __launch_bounds__(128) void ct_rmsnorm_h(const float2* __restrict__ in,
                                                    const float2* __restrict__ gamma,
                                                    __half* __restrict__ outre,
                                                    __half* __restrict__ outim) {
    int row = blockIdx.x;
    const float2* xr = in + row*DIMC;
    float ss = 0.f;
    for (int d = threadIdx.x; d < DIMC; d += 128) {
        float2 v = xr[d];
        ss = fmaf(v.x, v.x, ss);
        ss = fmaf(v.y, v.y, ss);
    }
#pragma unroll
    for (int off = 16; off; off >>= 1) ss += __shfl_xor_sync(0xffffffffu, ss, off);
    __shared__ float sred[4];
    if ((threadIdx.x & 31) == 0) sred[threadIdx.x >> 5] = ss;
    __syncthreads();
    ss = sred[0] + sred[1] + sred[2] + sred[3];
    float sc = rsqrtf(ss * (1.f/(float)DIMC) + EPSF);
    for (int d = threadIdx.x; d < DIMC; d += 128) {
        float2 v = xr[d];
        float2 gm = gamma[d];
        outre[row*DIMC + d] = __float2half(sc*(v.x*gm.x - v.y*gm.y));
        outim[row*DIMC + d] = __float2half(sc*(v.x*gm.y + v.y*gm.x));
    }
}

// ---------------- final rmsnorm -> float2 output ----------------
__global__ __launch_bounds__(128) void ct_rmsnorm_f(const float2* __restrict__ in,
                                                    const float2* __restrict__ gamma,
                                                    float2* __restrict__ out) {
    int row = blockIdx.x;
    const float2* xr = in + row*DIMC;
    float ss = 0.f;
    for (int d = threadIdx.x; d < DIMC; d += 128) {
        float2 v = xr[d];
        ss = fmaf(v.x, v.x, ss);
        ss = fmaf(v.y, v.y, ss);
    }
#pragma unroll
    for (int off = 16; off; off >>= 1) ss += __shfl_xor_sync(0xffffffffu, ss, off);
    __shared__ float sred[4];
    if ((threadIdx.x & 31) == 0) sred[threadIdx.x >> 5] = ss;
    __syncthreads();
    ss = sred[0] + sred[1] + sred[2] + sred[3];
    float sc = rsqrtf(ss * (1.f/(float)DIMC) + EPSF);
    for (int d = threadIdx.x; d < DIMC; d += 128) {
        float2 v = xr[d];
        float2 gm = gamma[d];
        out[row*DIMC + d] = make_float2(sc*(v.x*gm.x - v.y*gm.y),
                                        sc*(v.x*gm.y + v.y*gm.x));
    }
}

// ---------------- fp16 complex GEMM, 2-stage cp.async ----------------
// A planes [m][k] half (k-contig), B planes [n][k] half. TBM=128,TBN=64,TBK=32.
#define TBM 128
#define TBN 64
#define AST 40          // halves per A row (32+8) -> conflict-free
#define BST 40
#define HG_STAGE 30720  // Are 10240 | Aim 10240 | Bre 5120 | Bim 5120
#define HG_SMEM  (2*HG_STAGE)

// epi: 0=Q rope  1=KV (K rope + V transposed)  2=residual  3=FF1  4=FF2+res
__device__ __forceinline__ void epilog_h(int m, int n, float re, float im, int epi,
                                         const float2* __restrict__ bias,
                                         const float* __restrict__ modb) {
    if (epi == 0) {
        float2 ph = g_rope[(m & (NN-1))*DHH + (n & (DHH-1))];
        float tr = re*ph.x - im*ph.y, ti = re*ph.y + im*ph.x;
        size_t idx = (size_t)m*INNERC + n;
        g_qre[idx] = __float2half(tr); g_qim[idx] = __float2half(ti);
    } else if (epi == 1) {
        if (n < INNERC) {
            float2 ph = g_rope[(m & (NN-1))*DHH + (n & (DHH-1))];
            float tr = re*ph.x - im*ph.y, ti = re*ph.y + im*ph.x;
            size_t idx = (size_t)m*INNERC + n;
            g_kre[idx] = __float2half(tr); g_kim[idx] = __float2half(ti);
        } else {
            int vv = n - INNERC;
            int b = m >> 10, tok = m & 1023;
            int h = vv >> 6, d = vv & 63;
            size_t idx = (size_t)(((b*NHEADS + h)*DHH + d))*NN + tok;
            g_vtre[idx] = __float2half(re); g_vtim[idx] = __float2half(im);
        }
    } else if (epi == 2) {
        size_t idx = (size_t)m*DIMC + n;
        float2 c = g_x[idx];
        g_x[idx] = make_float2(c.x + re, c.y + im);
    } else if (epi == 3) {
        float2 bv = bias[n];
        float rx = re + bv.x, ry = im + bv.y;
        float mag = sqrtf(rx*rx + ry*ry);
        float t = fmaxf(mag + *modb, 0.f);
        float cl = t*t;
        if (mag > 0.f) { float s = cl/mag; rx *= s; ry *= s; }
        else           { rx = cl; ry = 0.f; }
        size_t idx = (size_t)m*FFC + n;
        g_fre[idx] = __float2half(rx); g_fim[idx] = __float2half(ry);
    } else {
        float2 bv = bias[n];
        size_t idx = (size_t)m*DIMC + n;
        float2 c = g_x[idx];
        g_x[idx] = make_float2(c.x + re + bv.x, c.y + im + bv.y);
    }
}

__global__ __launch_bounds__(256, 2) void ct_hgemm(const __half* __restrict__ Are_g,
                                                   const __half* __restrict__ Aim_g,
                                                   const __half* __restrict__ Wre_g,
                                                   int K, int NC, int epi,
                                                   const float2* __restrict__ bias,
                                                   const float* __restrict__ modb) {
    extern __shared__ char dynsm[];
    const __half* Wim_g = Wre_g + (size_t)NC*K;
    int tid = threadIdx.x, warp = tid >> 5, lane = tid & 31;
    int g = lane >> 2, tg = lane & 3;
    int warp_m = warp & 3, warp_n = warp >> 2;
    int m0 = blockIdx.y * TBM, n0 = blockIdx.x * TBN;
    uint32_t smbase = (uint32_t)__cvta_generic_to_shared(dynsm);

    float cr[2][4][4] = {};
    float ci[2][4][4] = {};
    const int ntiles = K / 32;

    auto stageLoad = [&](int s, int k0) {
        uint32_t base = smbase + s*HG_STAGE;
#pragma unroll
        for (int i = 0; i < 4; i++) {        // A: 128 rows x 2 planes x 4 chunks
            int e = tid + i*256;
            int plane = e >> 9;
            int r = (e >> 2) & 127;
            int c = e & 3;
            const __half* src = (plane ? Aim_g : Are_g) + (size_t)(m0 + r)*K + k0 + c*8;
            cp16(base + plane*10240 + r*80 + c*16, src);
        }
#pragma unroll
        for (int i = 0; i < 2; i++) {        // B: 64 rows x 2 planes x 4 chunks
            int e = tid + i*256;
            int plane = e >> 8;
            int r = (e >> 2) & 63;
            int c = e & 3;
            const __half* src = (plane ? Wim_g : Wre_g) + (size_t)(n0 + r)*K + k0 + c*8;
            cp16(base + 20480 + plane*5120 + r*80 + c*16, src);
        }
        cp_commit();
    };

    stageLoad(0, 0);
    for (int kt = 0; kt < ntiles; kt++) {
        if (kt + 1 < ntiles) { stageLoad((kt+1)&1, (kt+1)*32); cp_wait<1>(); }
        else                 { cp_wait<0>(); }
        __syncthreads();

        const __half* Asre = (const __half*)(dynsm + (kt&1)*HG_STAGE);
        const __half* Asim = Asre + 5120;
        const __half* Bsre = (const __half*)(dynsm + (kt&1)*HG_STAGE + 20480);
        const __half* Bsim = Bsre + 2560;

#pragma unroll
        for (int ks = 0; ks < 2; ks++) {
            int kb = ks*16;
            uint32_t ar[2][4], ai_[2][4], nai[2][4];
#pragma unroll
            for (int mt = 0; mt < 2; mt++) {
                int mb = warp_m*32 + mt*16;
                int i0 = (mb + g    )*AST + kb + 2*tg;
                int i1 = (mb + g + 8)*AST + kb + 2*tg;
                ar[mt][0] = *(const uint32_t*)&Asre[i0];
                ar[mt][1] = *(const uint32_t*)&Asre[i1];
                ar[mt][2] = *(const uint32_t*)&Asre[i0 + 8];
                ar[mt][3] = *(const uint32_t*)&Asre[i1 + 8];
                ai_[mt][0] = *(const uint32_t*)&Asim[i0];
                ai_[mt][1] = *(const uint32_t*)&Asim[i1];
                ai_[mt][2] = *(const uint32_t*)&Asim[i0 + 8];
                ai_[mt][3] = *(const uint32_t*)&Asim[i1 + 8];
#pragma unroll
                for (int t = 0; t < 4; t++) nai[mt][t] = ai_[mt][t] ^ 0x80008000u;
            }
            uint32_t br[4][2], bi[4][2];
#pragma unroll
            for (int nt = 0; nt < 4; nt++) {
                int ib = (warp_n*32 + nt*8 + g)*BST + kb + 2*tg;
                br[nt][0] = *(const uint32_t*)&Bsre[ib];
                br[nt][1] = *(const uint32_t*)&Bsre[ib + 8];
                bi[nt][0] = *(const uint32_t*)&Bsim[ib];
                bi[nt][1] = *(const uint32_t*)&Bsim[ib + 8];
            }
#pragma unroll
            for (int mt = 0; mt < 2; mt++)
#pragma unroll
                for (int nt = 0; nt < 4; nt++) {
                    mma_f16(cr[mt][nt], ar[mt],  br[nt]);
                    mma_f16(cr[mt][nt], nai[mt], bi[nt]);
                    mma_f16(ci[mt][nt], ar[mt],  bi[nt]);
                    mma_f16(ci[mt][nt], ai_[mt], br[nt]);
                }
        }
        __syncthreads();
    }

#pragma unroll
    for (int mt = 0; mt < 2; mt++)
#pragma unroll
        for (int nt = 0; nt < 4; nt++)
#pragma unroll
            for (int c = 0; c < 4; c++) {
                int row = m0 + warp_m*32 + mt*16 + g + ((c >= 2) ? 8 : 0);
                int col = n0 + warp_n*32 + nt*8 + 2*tg + (c & 1);
                epilog_h(row, col, cr[mt][nt][c], ci[mt][nt][c], epi, bias, modb);
            }
}

// ---------------- fp16 merged-variant attention ----------------
// grid (bh=16, qtile=32), block 256 = 8 warps = (variant) x (q-half).
#define AQ2 32
#define AK2 16
#define KST 72      // halves per K row
#define VST 24      // halves per V row
#define QST 72
#define PST2 24
#define AKV_STAGE 10752   // K: 2x16x72x2=4608 | V: 2x64x24x2=6144
#define AT_QOFF   21504   // Q: 2x32x72x2=9216  (P aliases this after frag load)
#define AT_SMEM   32768   // combine planes (4x32x64 f32 = 32768) alias everything

__global__ __launch_bounds__(256, 2) void ct_attn_h() {
    extern __shared__ char asmem[];
    int bh = blockIdx.x;
    int b  = bh >> 3;
    int h  = bh & 7;
    int q0 = blockIdx.y * AQ2;
    int tid = threadIdx.x, warp = tid >> 5, lane = tid & 31;
    int g = lane >> 2, tg = lane & 3;
    int v  = warp & 3;
    int qh = warp >> 2;
    int m0 = qh * 16;
    uint32_t smbase = (uint32_t)__cvta_generic_to_shared(asmem);

    // ---- stage Q planes ----
#pragma unroll
    for (int i = 0; i < 2; i++) {
        int e = tid + i*256;
        int plane = e >> 8;
        int row = (e >> 3) & 31;
        int c = e & 7;
        const __half* src = (plane ? g_qim : g_qre) +
            (size_t)(b*NN + q0 + row)*INNERC + h*DHH + c*8;
        cp16(smbase + AT_QOFF + plane*4608 + row*144 + c*16, src);
    }
    cp_commit();

    auto loadKV = [&](int s, int kt) {
        uint32_t base = smbase + s*AKV_STAGE;
        {   // K: 16 rows x 2 planes x 8 chunks = 256 cp16
            int e = tid;
            int plane = e >> 7;
            int row = (e >> 3) & 15;
            int c = e & 7;
            const __half* src = (plane ? g_kim : g_kre) +
                (size_t)(b*NN + kt + row)*INNERC + h*DHH + c*8;
            cp16(base + plane*2304 + row*144 + c*16, src);
        }
        {   // V: 64 d-rows x 2 planes x 2 chunks = 256 cp16
            int e = tid;
            int plane = e >> 7;
            int row = (e >> 1) & 63;
            int c = e & 1;
            const __half* src = (plane ? g_vtim : g_vtre) +
                (size_t)(bh*DHH + row)*NN + kt + c*8;
            cp16(base + 4608 + plane*3072 + row*48 + c*16, src);
        }
        cp_commit();
    };

    loadKV(0, 0);
    cp_wait<1>();     // Q done
    __syncthreads();

    // ---- Q fragments (variant-selected plane) ----
    const __half* Qs = (const __half*)(asmem + AT_QOFF + ((v < 2) ? 0 : 4608));
    uint32_t qa[4][4];
#pragma unroll
    for (int ks = 0; ks < 4; ks++) {
        int i0 = (m0 + g    )*QST + ks*16 + 2*tg;
        int i1 = (m0 + g + 8)*QST + ks*16 + 2*tg;
        qa[ks][0] = *(const uint32_t*)&Qs[i0];
        qa[ks][1] = *(const uint32_t*)&Qs[i1];
        qa[ks][2] = *(const uint32_t*)&Qs[i0 + 8];
        qa[ks][3] = *(const uint32_t*)&Qs[i1 + 8];
    }
    __syncthreads();   // Q region dead -> P may reuse

    __half* Ps = (__half*)(asmem + AT_QOFF) + warp * (16 * PST2);

    float o[8][4] = {};
    float lsum_lo = 0.f, lsum_hi = 0.f;
    const int ntiles = NN / AK2;

    for (int t = 0; t < ntiles; t++) {
        if (t + 1 < ntiles) { loadKV((t+1)&1, (t+1)*AK2); cp_wait<1>(); }
        else                { cp_wait<0>(); }
        __syncthreads();

        const char* stage = asmem + (t&1)*AKV_STAGE;
        const __half* Ks = (const __half*)(stage + ((v & 1) ? 2304 : 0));
        const __half* Vs = (const __half*)(stage + 4608 + ((v < 2) ? 0 : 3072));

        // ---- S = q k^T (m16 x n16 x k64) ----
        float sacc[2][4] = {};
#pragma unroll
        for (int ks = 0; ks < 4; ks++) {
#pragma unroll
            for (int nt = 0; nt < 2; nt++) {
                int ib = (nt*8 + g)*KST + ks*16 + 2*tg;
                uint32_t bb[2];
                bb[0] = *(const uint32_t*)&Ks[ib];
                bb[1] = *(const uint32_t*)&Ks[ib + 8];
                if (v & 1) { bb[0] ^= 0x80008000u; bb[1] ^= 0x80008000u; }
                mma_f16(sacc[nt], qa[ks], bb);
            }
        }

        // ---- exp -> half P; row sums in fp32 ----
#pragma unroll
        for (int nt = 0; nt < 2; nt++) {
            float p0 = __expf(sacc[nt][0] * ATT_SCALE);
            float p1 = __expf(sacc[nt][1] * ATT_SCALE);
            float p2 = __expf(sacc[nt][2] * ATT_SCALE);
            float p3 = __expf(sacc[nt][3] * ATT_SCALE);
            lsum_lo += p0 + p1;
            lsum_hi += p2 + p3;
            __half2 h01 = __floats2half2_rn(p0, p1);
            __half2 h23 = __floats2half2_rn(p2, p3);
            *(uint32_t*)&Ps[(g    )*PST2 + nt*8 + 2*tg] = *(uint32_t*)&h01;
            *(uint32_t*)&Ps[(g + 8)*PST2 + nt*8 + 2*tg] = *(uint32_t*)&h23;
        }
        __syncwarp();

        // ---- O += P V (m16 x n64 x k16) ----
        uint32_t pa[4];
        pa[0] = *(const uint32_t*)&Ps[(g    )*PST2 + 2*tg];
        pa[1] = *(const uint32_t*)&Ps[(g + 8)*PST2 + 2*tg];
        pa[2] = *(const uint32_t*)&Ps[(g    )*PST2 + 2*tg + 8];
        pa[3] = *(const uint32_t*)&Ps[(g + 8)*PST2 + 2*tg + 8];
#pragma unroll
        for (int nt = 0; nt < 8; nt++) {
            int ib = (nt*8 + g)*VST + 2*tg;
            uint32_t bb[2];
            bb[0] = *(const uint32_t*)&Vs[ib];
            bb[1] = *(const uint32_t*)&Vs[ib + 8];
            mma_f16(o[nt], pa, bb);
        }
        __syncthreads();
    }

    // ---- row sums, normalize, write fp32 variant planes (alias smem) ----
#pragma unroll
    for (int off = 1; off <= 2; off <<= 1) {
        lsum_lo += __shfl_xor_sync(0xffffffffu, lsum_lo, off);
        lsum_hi += __shfl_xor_sync(0xffffffffu, lsum_hi, off);
    }
    float inv_lo = 1.f / lsum_lo;
    float inv_hi = 1.f / lsum_hi;
    float* pl = (float*)asmem + v * (AQ2 * DHH);
#pragma unroll
    for (int nt = 0; nt < 8; nt++) {
        int col = nt*8 + 2*tg;
        pl[(m0 + g    )*DHH + col    ] = o[nt][0] * inv_lo;
        pl[(m0 + g    )*DHH + col + 1] = o[nt][1] * inv_lo;
        pl[(m0 + g + 8)*DHH + col    ] = o[nt][2] * inv_hi;
        pl[(m0 + g + 8)*DHH + col + 1] = o[nt][3] * inv_hi;
    }
    __syncthreads();

    // ---- combine: re = o0 - o3, im = o1 + o2 -> half planes ----
    const float* planes = (const float*)asmem;
#pragma unroll
    for (int i = 0; i < 8; i++) {
        int e = tid + i*256;
        int row = e >> 6, d = e & 63;
        float re = planes[             row*DHH + d] - planes[3*AQ2*DHH + row*DHH + d];
        float im = planes[  AQ2*DHH + row*DHH + d] + planes[2*AQ2*DHH + row*DHH + d];
        size_t idx = (size_t)(b*NN + q0 + row)*INNERC + h*DHH + d;
        g_ore[idx] = __float2half(re);
        g_oim[idx] = __float2half(im);
    }
}

// ---------------- launcher ----------------
extern "C" void kernel_launch(void* const* d_in, const int* in_sizes, int n_in,
                              void* d_out, int out_size) {
    (void)in_sizes; (void)n_in; (void)out_size;
    const float2* x          = (const float2*)d_in[0];
    const float2* gamma_attn = (const float2*)d_in[1];
    const float2* Wq         = (const float2*)d_in[2];
    const float2* Wkv        = (const float2*)d_in[3];
    const float2* Wo         = (const float2*)d_in[4];
    const float2* gamma_ff   = (const float2*)d_in[5];
    const float2* W1         = (const float2*)d_in[6];
    const float2* b1         = (const float2*)d_in[7];
    const float*  modb       = (const float*)d_in[8];
    const float2* W2         = (const float2*)d_in[9];
    const float2* b2         = (const float2*)d_in[10];
    const float2* gfin       = (const float2*)d_in[11];

    float2* px;
    __half *phre, *phim, *pore, *poim, *pfre, *pfim, *pwh;
    cudaGetSymbolAddress((void**)&px,   g_x);
    cudaGetSymbolAddress((void**)&phre, g_hre);
    cudaGetSymbolAddress((void**)&phim, g_him);
    cudaGetSymbolAddress((void**)&pore, g_ore);
    cudaGetSymbolAddress((void**)&poim, g_oim);
    cudaGetSymbolAddress((void**)&pfre, g_fre);
    cudaGetSymbolAddress((void**)&pfim, g_fim);
    cudaGetSymbolAddress((void**)&pwh,  g_wh);

    cudaFuncSetAttribute(ct_hgemm,  cudaFuncAttributeMaxDynamicSharedMemorySize, HG_SMEM);
    cudaFuncSetAttribute(ct_attn_h, cudaFuncAttributeMaxDynamicSharedMemorySize, AT_SMEM);

    cudaMemcpyAsync(px, x, sizeof(float2)*MM*DIMC, cudaMemcpyDeviceToDevice);
    ct_rope_init<<<(NN*DHH + 255)/256, 256>>>();

    // weight prep: transpose + convert to half planes
    ct_wprep<<<dim3(512/32,  512/32,  2), 256>>>(Wq,  pwh + WQ_OFF,  512,  512);
    ct_wprep<<<dim3(1024/32, 512/32,  2), 256>>>(Wkv, pwh + WKV_OFF, 512,  1024);
    ct_wprep<<<dim3(512/32,  512/32,  2), 256>>>(Wo,  pwh + WO_OFF,  512,  512);
    ct_wprep<<<dim3(2048/32, 512/32,  2), 256>>>(W1,  pwh + W1_OFF,  512,  2048);
    ct_wprep<<<dim3(512/32,  2048/32, 2), 256>>>(W2,  pwh + W2_OFF,  2048, 512);

    for (int l = 0; l < NDEPTH; l++) {
        ct_rmsnorm_h<<<MM, 128>>>(px, gamma_attn + l*DIMC, phre, phim);
        ct_hgemm<<<dim3(INNERC/TBN, MM/TBM), 256, HG_SMEM>>>(
            phre, phim, pwh + WQ_OFF + (size_t)l*524288, 512, INNERC, 0, nullptr, nullptr);
        ct_hgemm<<<dim3(1024/TBN, MM/TBM), 256, HG_SMEM>>>(
            phre, phim, pwh + WKV_OFF + (size_t)l*1048576, 512, 1024, 1, nullptr, nullptr);
        ct_attn_h<<<dim3(BB*NHEADS, NN/AQ2), 256, AT_SMEM>>>();
        ct_hgemm<<<dim3(DIMC/TBN, MM/TBM), 256, HG_SMEM>>>(
            pore, poim, pwh + WO_OFF + (size_t)l*524288, 512, DIMC, 2, nullptr, nullptr);
        ct_rmsnorm_h<<<MM, 128>>>(px, gamma_ff + l*DIMC, phre, phim);
        ct_hgemm<<<dim3(FFC/TBN, MM/TBM), 256, HG_SMEM>>>(
            phre, phim, pwh + W1_OFF + (size_t)l*2097152, 512, FFC, 3, b1 + l*FFC, modb + l);
        ct_hgemm<<<dim3(DIMC/TBN, MM/TBM), 256, HG_SMEM>>>(
            pfre, pfim, pwh + W2_OFF + (size_t)l*2097152, 2048, DIMC, 4, b2 + l*DIMC, nullptr);
    }
    ct_rmsnorm_f<<<MM, 128>>>(px, gfin, (float2*)d_out);
}

// round 15
// speedup vs baseline: 1.8166x; 1.0056x over previous
#include <cuda_runtime.h>
#include <cuda_fp16.h>
#include <math.h>
#include <stdint.h>

#define BB     2
#define NN     1024
#define DIMC   512
#define NHEADS 8
#define DHH    64
#define INNERC 512
#define FFC    2048
#define NDEPTH 2
#define MM     (BB*NN)
#define EPSF   1e-6f
#define ATT_SCALE 0.125f

// ---------------- scratch ----------------
__device__ float2 g_x [MM*DIMC];          // residual (fp32)
__device__ float2 g_rope[NN*DHH];
__device__ __half g_hre[MM*DIMC],   g_him[MM*DIMC];    // rmsnorm out
__device__ __half g_qre[MM*INNERC], g_qim[MM*INNERC];  // Q (roped)
__device__ __half g_kre[MM*INNERC], g_kim[MM*INNERC];  // K (roped)
__device__ __half g_vtre[MM*INNERC], g_vtim[MM*INNERC];// V transposed [bh][d][tok]
__device__ __half g_ore[MM*INNERC], g_oim[MM*INNERC];  // attention out
__device__ __half g_fre[MM*FFC],    g_fim[MM*FFC];     // FF intermediate
__device__ __half g_wh[12582912];                      // all weights, [n][k] re|im planes

#define WQ_OFF  0u
#define WKV_OFF 1048576u
#define WO_OFF  3145728u
#define W1_OFF  4194304u
#define W2_OFF  8388608u

__device__ __forceinline__ void mma_f16(float* d, const uint32_t* a, const uint32_t* b) {
    asm volatile(
        "mma.sync.aligned.m16n8k16.row.col.f32.f16.f16.f32 "
        "{%0,%1,%2,%3},{%4,%5,%6,%7},{%8,%9},{%0,%1,%2,%3};"
        : "+f"(d[0]), "+f"(d[1]), "+f"(d[2]), "+f"(d[3])
        : "r"(a[0]), "r"(a[1]), "r"(a[2]), "r"(a[3]), "r"(b[0]), "r"(b[1]));
}
__device__ __forceinline__ void cp16(uint32_t dst, const void* src) {
    asm volatile("cp.async.cg.shared.global [%0], [%1], 16;" :: "r"(dst), "l"(src));
}
__device__ __forceinline__ void cp_commit() { asm volatile("cp.async.commit_group;"); }
template<int N> __device__ __forceinline__ void cp_wait() {
    asm volatile("cp.async.wait_group %0;" :: "n"(N));
}

// ---------------- weight prep: transpose + fp16 convert ----------------
__global__ __launch_bounds__(256) void ct_wprep(const float2* __restrict__ src,
                                                __half* __restrict__ dst, int K, int N) {
    int l = blockIdx.z;
    src += (size_t)l*K*N;
    dst += (size_t)l*2*N*K;
    __shared__ float2 tile[32][33];
    int n0 = blockIdx.x*32, k0 = blockIdx.y*32;
    int tx = threadIdx.x & 31, ty = threadIdx.x >> 5;
    for (int i = ty; i < 32; i += 8)
        tile[i][tx] = src[(size_t)(k0+i)*N + n0 + tx];
    __syncthreads();
    for (int i = ty; i < 32; i += 8) {
        float2 v = tile[tx][i];
        size_t o = (size_t)(n0+i)*K + k0 + tx;
        dst[o] = __float2half(v.x);
        dst[(size_t)N*K + o] = __float2half(v.y);
    }
}

// ---------------- rope table ----------------
__global__ void ct_rope_init() {
    int i = blockIdx.x*blockDim.x + threadIdx.x;
    if (i >= NN*DHH) return;
    int n = i / DHH, d = i % DHH;
    double inv = exp(-((double)d / (double)DHH) * log(10000.0));
    double fr  = (double)n * inv;
    g_rope[i] = make_float2((float)cos(fr), (float)sin(fr));
}

// ---------------- complex rmsnorm -> half planes ----------------
__global__ __launch_bounds__(128) void ct_rmsnorm_h(const float2* __restrict__ in,
                                                    const float2* __restrict__ gamma,
                                                    __half* __restrict__ outre,
                                                    __half* __restrict__ outim) {
    int row = blockIdx.x;
    const float2* xr = in + row*DIMC;
    float ss = 0.f;
    for (int d = threadIdx.x; d < DIMC; d += 128) {
        float2 v = xr[d];
        ss = fmaf(v.x, v.x, ss);
        ss = fmaf(v.y, v.y, ss);
    }
#pragma unroll
    for (int off = 16; off; off >>= 1) ss += __shfl_xor_sync(0xffffffffu, ss, off);
    __shared__ float sred[4];
    if ((threadIdx.x & 31) == 0) sred[threadIdx.x >> 5] = ss;
    __syncthreads();
    ss = sred[0] + sred[1] + sred[2] + sred[3];
    float sc = rsqrtf(ss * (1.f/(float)DIMC) + EPSF);
    for (int d = threadIdx.x; d < DIMC; d += 128) {
        float2 v = xr[d];
        float2 gm = gamma[d];
        outre[row*DIMC + d] = __float2half(sc*(v.x*gm.x - v.y*gm.y));
        outim[row*DIMC + d] = __float2half(sc*(v.x*gm.y + v.y*gm.x));
    }
}

// ---------------- final rmsnorm -> float2 output ----------------
__global__ __launch_bounds__(128) void ct_rmsnorm_f(const float2* __restrict__ in,
                                                    const float2* __restrict__ gamma,
                                                    float2* __restrict__ out) {
    int row = blockIdx.x;
    const float2* xr = in + row*DIMC;
    float ss = 0.f;
    for (int d = threadIdx.x; d < DIMC; d += 128) {
        float2 v = xr[d];
        ss = fmaf(v.x, v.x, ss);
        ss = fmaf(v.y, v.y, ss);
    }
#pragma unroll
    for (int off = 16; off; off >>= 1) ss += __shfl_xor_sync(0xffffffffu, ss, off);
    __shared__ float sred[4];
    if ((threadIdx.x & 31) == 0) sred[threadIdx.x >> 5] = ss;
    __syncthreads();
    ss = sred[0] + sred[1] + sred[2] + sred[3];
    float sc = rsqrtf(ss * (1.f/(float)DIMC) + EPSF);
    for (int d = threadIdx.x; d < DIMC; d += 128) {
        float2 v = xr[d];
        float2 gm = gamma[d];
        out[row*DIMC + d] = make_float2(sc*(v.x*gm.x - v.y*gm.y),
                                        sc*(v.x*gm.y + v.y*gm.x));
    }
}

// ---------------- fp16 complex GEMM, 2-stage cp.async, templated TBM --------
// MT = m-tiles per warp. TBM = 64*MT. TBN = 64. TBK = 32.
#define TBN 64
#define AST 40
#define BST 40

// epi: 0=Q rope  1=KV (K rope + V transposed)  2=residual  3=FF1  4=FF2+res
__device__ __forceinline__ void epilog_h(int m, int n, float re, float im, int epi,
                                         const float2* __restrict__ bias,
                                         const float* __restrict__ modb) {
    if (epi == 0) {
        float2 ph = g_rope[(m & (NN-1))*DHH + (n & (DHH-1))];
        float tr = re*ph.x - im*ph.y, ti = re*ph.y + im*ph.x;
        size_t idx = (size_t)m*INNERC + n;
        g_qre[idx] = __float2half(tr); g_qim[idx] = __float2half(ti);
    } else if (epi == 1) {
        if (n < INNERC) {
            float2 ph = g_rope[(m & (NN-1))*DHH + (n & (DHH-1))];
            float tr = re*ph.x - im*ph.y, ti = re*ph.y + im*ph.x;
            size_t idx = (size_t)m*INNERC + n;
            g_kre[idx] = __float2half(tr); g_kim[idx] = __float2half(ti);
        } else {
            int vv = n - INNERC;
            int b = m >> 10, tok = m & 1023;
            int h = vv >> 6, d = vv & 63;
            size_t idx = (size_t)(((b*NHEADS + h)*DHH + d))*NN + tok;
            g_vtre[idx] = __float2half(re); g_vtim[idx] = __float2half(im);
        }
    } else if (epi == 2) {
        size_t idx = (size_t)m*DIMC + n;
        float2 c = g_x[idx];
        g_x[idx] = make_float2(c.x + re, c.y + im);
    } else if (epi == 3) {
        float2 bv = bias[n];
        float rx = re + bv.x, ry = im + bv.y;
        float mag = sqrtf(rx*rx + ry*ry);
        float t = fmaxf(mag + *modb, 0.f);
        float cl = t*t;
        if (mag > 0.f) { float s = cl/mag; rx *= s; ry *= s; }
        else           { rx = cl; ry = 0.f; }
        size_t idx = (size_t)m*FFC + n;
        g_fre[idx] = __float2half(rx); g_fim[idx] = __float2half(ry);
    } else {
        float2 bv = bias[n];
        size_t idx = (size_t)m*DIMC + n;
        float2 c = g_x[idx];
        g_x[idx] = make_float2(c.x + re + bv.x, c.y + im + bv.y);
    }
}

template<int MT>
__global__ __launch_bounds__(256, 2) void ct_hgemm(const __half* __restrict__ Are_g,
                                                   const __half* __restrict__ Aim_g,
                                                   const __half* __restrict__ Wre_g,
                                                   int K, int NC, int epi,
                                                   const float2* __restrict__ bias,
                                                   const float* __restrict__ modb) {
    constexpr int TBMv = 64*MT;
    constexpr int STAGE = 2*TBMv*80 + 10240;   // A planes + B planes (bytes)
    extern __shared__ char dynsm[];
    const __half* Wim_g = Wre_g + (size_t)NC*K;
    int tid = threadIdx.x, warp = tid >> 5, lane = tid & 31;
    int g = lane >> 2, tg = lane & 3;
    int warp_m = warp & 3, warp_n = warp >> 2;
    int m0 = blockIdx.y * TBMv, n0 = blockIdx.x * TBN;
    uint32_t smbase = (uint32_t)__cvta_generic_to_shared(dynsm);

    float cr[MT][4][4] = {};
    float ci[MT][4][4] = {};
    const int ntiles = K / 32;

    auto stageLoad = [&](int s, int k0) {
        uint32_t base = smbase + s*STAGE;
#pragma unroll
        for (int i = 0; i < TBMv/32; i++) {        // A: TBMv rows x 2 planes x 4 chunks
            int e = tid + i*256;
            int plane = e / (TBMv*4);
            int r = (e >> 2) & (TBMv - 1);
            int c = e & 3;
            const __half* src = (plane ? Aim_g : Are_g) + (size_t)(m0 + r)*K + k0 + c*8;
            cp16(base + plane*(TBMv*80) + r*80 + c*16, src);
        }
#pragma unroll
        for (int i = 0; i < 2; i++) {              // B: 64 rows x 2 planes x 4 chunks
            int e = tid + i*256;
            int plane = e >> 8;
            int r = (e >> 2) & 63;
            int c = e & 3;
            const __half* src = (plane ? Wim_g : Wre_g) + (size_t)(n0 + r)*K + k0 + c*8;
            cp16(base + 2*TBMv*80 + plane*5120 + r*80 + c*16, src);
        }
        cp_commit();
    };

    stageLoad(0, 0);
    for (int kt = 0; kt < ntiles; kt++) {
        if (kt + 1 < ntiles) { stageLoad((kt+1)&1, (kt+1)*32); cp_wait<1>(); }
        else                 { cp_wait<0>(); }
        __syncthreads();

        const __half* Asre = (const __half*)(dynsm + (kt&1)*STAGE);
        const __half* Asim = Asre + TBMv*40;
        const __half* Bsre = Asre + TBMv*80;
        const __half* Bsim = Bsre + 2560;

#pragma unroll
        for (int ks = 0; ks < 2; ks++) {
            int kb = ks*16;
            uint32_t ar[MT][4], ai_[MT][4], nai[MT][4];
#pragma unroll
            for (int mt = 0; mt < MT; mt++) {
                int mb = warp_m*(16*MT) + mt*16;
                int i0 = (mb + g    )*AST + kb + 2*tg;
                int i1 = (mb + g + 8)*AST + kb + 2*tg;
                ar[mt][0] = *(const uint32_t*)&Asre[i0];
                ar[mt][1] = *(const uint32_t*)&Asre[i1];
                ar[mt][2] = *(const uint32_t*)&Asre[i0 + 8];
                ar[mt][3] = *(const uint32_t*)&Asre[i1 + 8];
                ai_[mt][0] = *(const uint32_t*)&Asim[i0];
                ai_[mt][1] = *(const uint32_t*)&Asim[i1];
                ai_[mt][2] = *(const uint32_t*)&Asim[i0 + 8];
                ai_[mt][3] = *(const uint32_t*)&Asim[i1 + 8];
#pragma unroll
                for (int t = 0; t < 4; t++) nai[mt][t] = ai_[mt][t] ^ 0x80008000u;
            }
            uint32_t br[4][2], bi[4][2];
#pragma unroll
            for (int nt = 0; nt < 4; nt++) {
                int ib = (warp_n*32 + nt*8 + g)*BST + kb + 2*tg;
                br[nt][0] = *(const uint32_t*)&Bsre[ib];
                br[nt][1] = *(const uint32_t*)&Bsre[ib + 8];
                bi[nt][0] = *(const uint32_t*)&Bsim[ib];
                bi[nt][1] = *(const uint32_t*)&Bsim[ib + 8];
            }
#pragma unroll
            for (int mt = 0; mt < MT; mt++)
#pragma unroll
                for (int nt = 0; nt < 4; nt++) {
                    mma_f16(cr[mt][nt], ar[mt],  br[nt]);
                    mma_f16(cr[mt][nt], nai[mt], bi[nt]);
                    mma_f16(ci[mt][nt], ar[mt],  bi[nt]);
                    mma_f16(ci[mt][nt], ai_[mt], br[nt]);
                }
        }
        __syncthreads();
    }

#pragma unroll
    for (int mt = 0; mt < MT; mt++)
#pragma unroll
        for (int nt = 0; nt < 4; nt++)
#pragma unroll
            for (int c = 0; c < 4; c++) {
                int row = m0 + warp_m*(16*MT) + mt*16 + g + ((c >= 2) ? 8 : 0);
                int col = n0 + warp_n*32 + nt*8 + 2*tg + (c & 1);
                epilog_h(row, col, cr[mt][nt][c], ci[mt][nt][c], epi, bias, modb);
            }
}

#define HG_SMEM1 (2*(2*64*80  + 10240))   // 40960
#define HG_SMEM2 (2*(2*128*80 + 10240))   // 61440

// ---------------- fp16 merged-variant attention ----------------
#define AQ2 32
#define AK2 16
#define KST 72
#define VST 24
#define QST 72
#define PST2 24
#define AKV_STAGE 10752
#define AT_QOFF   21504
#define AT_SMEM   32768

__global__ __launch_bounds__(256, 2) void ct_attn_h() {
    extern __shared__ char asmem[];
    int bh = blockIdx.x;
    int b  = bh >> 3;
    int h  = bh & 7;
    int q0 = blockIdx.y * AQ2;
    int tid = threadIdx.x, warp = tid >> 5, lane = tid & 31;
    int g = lane >> 2, tg = lane & 3;
    int v  = warp & 3;
    int qh = warp >> 2;
    int m0 = qh * 16;
    uint32_t smbase = (uint32_t)__cvta_generic_to_shared(asmem);

#pragma unroll
    for (int i = 0; i < 2; i++) {
        int e = tid + i*256;
        int plane = e >> 8;
        int row = (e >> 3) & 31;
        int c = e & 7;
        const __half* src = (plane ? g_qim : g_qre) +
            (size_t)(b*NN + q0 + row)*INNERC + h*DHH + c*8;
        cp16(smbase + AT_QOFF + plane*4608 + row*144 + c*16, src);
    }
    cp_commit();

    auto loadKV = [&](int s, int kt) {
        uint32_t base = smbase + s*AKV_STAGE;
        {
            int e = tid;
            int plane = e >> 7;
            int row = (e >> 3) & 15;
            int c = e & 7;
            const __half* src = (plane ? g_kim : g_kre) +
                (size_t)(b*NN + kt + row)*INNERC + h*DHH + c*8;
            cp16(base + plane*2304 + row*144 + c*16, src);
        }
        {
            int e = tid;
            int plane = e >> 7;
            int row = (e >> 1) & 63;
            int c = e & 1;
            const __half* src = (plane ? g_vtim : g_vtre) +
                (size_t)(bh*DHH + row)*NN + kt + c*8;
            cp16(base + 4608 + plane*3072 + row*48 + c*16, src);
        }
        cp_commit();
    };

    loadKV(0, 0);
    cp_wait<1>();
    __syncthreads();

    const __half* Qs = (const __half*)(asmem + AT_QOFF + ((v < 2) ? 0 : 4608));
    uint32_t qa[4][4];
#pragma unroll
    for (int ks = 0; ks < 4; ks++) {
        int i0 = (m0 + g    )*QST + ks*16 + 2*tg;
        int i1 = (m0 + g + 8)*QST + ks*16 + 2*tg;
        qa[ks][0] = *(const uint32_t*)&Qs[i0];
        qa[ks][1] = *(const uint32_t*)&Qs[i1];
        qa[ks][2] = *(const uint32_t*)&Qs[i0 + 8];
        qa[ks][3] = *(const uint32_t*)&Qs[i1 + 8];
    }
    __syncthreads();

    __half* Ps = (__half*)(asmem + AT_QOFF) + warp * (16 * PST2);

    float o[8][4] = {};
    float lsum_lo = 0.f, lsum_hi = 0.f;
    const int ntiles = NN / AK2;

    for (int t = 0; t < ntiles; t++) {
        if (t + 1 < ntiles) { loadKV((t+1)&1, (t+1)*AK2); cp_wait<1>(); }
        else                { cp_wait<0>(); }
        __syncthreads();

        const char* stage = asmem + (t&1)*AKV_STAGE;
        const __half* Ks = (const __half*)(stage + ((v & 1) ? 2304 : 0));
        const __half* Vs = (const __half*)(stage + 4608 + ((v < 2) ? 0 : 3072));

        float sacc[2][4] = {};
#pragma unroll
        for (int ks = 0; ks < 4; ks++) {
#pragma unroll
            for (int nt = 0; nt < 2; nt++) {
                int ib = (nt*8 + g)*KST + ks*16 + 2*tg;
                uint32_t bb[2];
                bb[0] = *(const uint32_t*)&Ks[ib];
                bb[1] = *(const uint32_t*)&Ks[ib + 8];
                if (v & 1) { bb[0] ^= 0x80008000u; bb[1] ^= 0x80008000u; }
                mma_f16(sacc[nt], qa[ks], bb);
            }
        }

#pragma unroll
        for (int nt = 0; nt < 2; nt++) {
            float p0 = __expf(sacc[nt][0] * ATT_SCALE);
            float p1 = __expf(sacc[nt][1] * ATT_SCALE);
            float p2 = __expf(sacc[nt][2] * ATT_SCALE);
            float p3 = __expf(sacc[nt][3] * ATT_SCALE);
            lsum_lo += p0 + p1;
            lsum_hi += p2 + p3;
            __half2 h01 = __floats2half2_rn(p0, p1);
            __half2 h23 = __floats2half2_rn(p2, p3);
            *(uint32_t*)&Ps[(g    )*PST2 + nt*8 + 2*tg] = *(uint32_t*)&h01;
            *(uint32_t*)&Ps[(g + 8)*PST2 + nt*8 + 2*tg] = *(uint32_t*)&h23;
        }
        __syncwarp();

        uint32_t pa[4];
        pa[0] = *(const uint32_t*)&Ps[(g    )*PST2 + 2*tg];
        pa[1] = *(const uint32_t*)&Ps[(g + 8)*PST2 + 2*tg];
        pa[2] = *(const uint32_t*)&Ps[(g    )*PST2 + 2*tg + 8];
        pa[3] = *(const uint32_t*)&Ps[(g + 8)*PST2 + 2*tg + 8];
#pragma unroll
        for (int nt = 0; nt < 8; nt++) {
            int ib = (nt*8 + g)*VST + 2*tg;
            uint32_t bb[2];
            bb[0] = *(const uint32_t*)&Vs[ib];
            bb[1] = *(const uint32_t*)&Vs[ib + 8];
            mma_f16(o[nt], pa, bb);
        }
        __syncthreads();
    }

#pragma unroll
    for (int off = 1; off <= 2; off <<= 1) {
        lsum_lo += __shfl_xor_sync(0xffffffffu, lsum_lo, off);
        lsum_hi += __shfl_xor_sync(0xffffffffu, lsum_hi, off);
    }
    float inv_lo = 1.f / lsum_lo;
    float inv_hi = 1.f / lsum_hi;
    float* pl = (float*)asmem + v * (AQ2 * DHH);
#pragma unroll
    for (int nt = 0; nt < 8; nt++) {
        int col = nt*8 + 2*tg;
        pl[(m0 + g    )*DHH + col    ] = o[nt][0] * inv_lo;
        pl[(m0 + g    )*DHH + col + 1] = o[nt][1] * inv_lo;
        pl[(m0 + g + 8)*DHH + col    ] = o[nt][2] * inv_hi;
        pl[(m0 + g + 8)*DHH + col + 1] = o[nt][3] * inv_hi;
    }
    __syncthreads();

    const float* planes = (const float*)asmem;
#pragma unroll
    for (int i = 0; i < 8; i++) {
        int e = tid + i*256;
        int row = e >> 6, d = e & 63;
        float re = planes[             row*DHH + d] - planes[3*AQ2*DHH + row*DHH + d];
        float im = planes[  AQ2*DHH + row*DHH + d] + planes[2*AQ2*DHH + row*DHH + d];
        size_t idx = (size_t)(b*NN + q0 + row)*INNERC + h*DHH + d;
        g_ore[idx] = __float2half(re);
        g_oim[idx] = __float2half(im);
    }
}

// ---------------- launcher ----------------
extern "C" void kernel_launch(void* const* d_in, const int* in_sizes, int n_in,
                              void* d_out, int out_size) {
    (void)in_sizes; (void)n_in; (void)out_size;
    const float2* x          = (const float2*)d_in[0];
    const float2* gamma_attn = (const float2*)d_in[1];
    const float2* Wq         = (const float2*)d_in[2];
    const float2* Wkv        = (const float2*)d_in[3];
    const float2* Wo         = (const float2*)d_in[4];
    const float2* gamma_ff   = (const float2*)d_in[5];
    const float2* W1         = (const float2*)d_in[6];
    const float2* b1         = (const float2*)d_in[7];
    const float*  modb       = (const float*)d_in[8];
    const float2* W2         = (const float2*)d_in[9];
    const float2* b2         = (const float2*)d_in[10];
    const float2* gfin       = (const float2*)d_in[11];

    float2* px;
    __half *phre, *phim, *pore, *poim, *pfre, *pfim, *pwh;
    cudaGetSymbolAddress((void**)&px,   g_x);
    cudaGetSymbolAddress((void**)&phre, g_hre);
    cudaGetSymbolAddress((void**)&phim, g_him);
    cudaGetSymbolAddress((void**)&pore, g_ore);
    cudaGetSymbolAddress((void**)&poim, g_oim);
    cudaGetSymbolAddress((void**)&pfre, g_fre);
    cudaGetSymbolAddress((void**)&pfim, g_fim);
    cudaGetSymbolAddress((void**)&pwh,  g_wh);

    cudaFuncSetAttribute(ct_hgemm<1>, cudaFuncAttributeMaxDynamicSharedMemorySize, HG_SMEM1);
    cudaFuncSetAttribute(ct_hgemm<2>, cudaFuncAttributeMaxDynamicSharedMemorySize, HG_SMEM2);
    cudaFuncSetAttribute(ct_attn_h,   cudaFuncAttributeMaxDynamicSharedMemorySize, AT_SMEM);

    cudaMemcpyAsync(px, x, sizeof(float2)*MM*DIMC, cudaMemcpyDeviceToDevice);
    ct_rope_init<<<(NN*DHH + 255)/256, 256>>>();

    ct_wprep<<<dim3(512/32,  512/32,  2), 256>>>(Wq,  pwh + WQ_OFF,  512,  512);
    ct_wprep<<<dim3(1024/32, 512/32,  2), 256>>>(Wkv, pwh + WKV_OFF, 512,  1024);
    ct_wprep<<<dim3(512/32,  512/32,  2), 256>>>(Wo,  pwh + WO_OFF,  512,  512);
    ct_wprep<<<dim3(2048/32, 512/32,  2), 256>>>(W1,  pwh + W1_OFF,  512,  2048);
    ct_wprep<<<dim3(512/32,  2048/32, 2), 256>>>(W2,  pwh + W2_OFF,  2048, 512);

    for (int l = 0; l < NDEPTH; l++) {
        ct_rmsnorm_h<<<MM, 128>>>(px, gamma_attn + l*DIMC, phre, phim);
        // N=512: MT=1 (TBM=64 -> 256 CTAs, full chip)
        ct_hgemm<1><<<dim3(INNERC/TBN, MM/64), 256, HG_SMEM1>>>(
            phre, phim, pwh + WQ_OFF + (size_t)l*524288, 512, INNERC, 0, nullptr, nullptr);
        // N=1024: MT=2 (256 CTAs already)
        ct_hgemm<2><<<dim3(1024/TBN, MM/128), 256, HG_SMEM2>>>(
            phre, phim, pwh + WKV_OFF + (size_t)l*1048576, 512, 1024, 1, nullptr, nullptr);
        ct_attn_h<<<dim3(BB*NHEADS, NN/AQ2), 256, AT_SMEM>>>();
        ct_hgemm<1><<<dim3(DIMC/TBN, MM/64), 256, HG_SMEM1>>>(
            pore, poim, pwh + WO_OFF + (size_t)l*524288, 512, DIMC, 2, nullptr, nullptr);
        ct_rmsnorm_h<<<MM, 128>>>(px, gamma_ff + l*DIMC, phre, phim);
        ct_hgemm<2><<<dim3(FFC/TBN, MM/128), 256, HG_SMEM2>>>(
            phre, phim, pwh + W1_OFF + (size_t)l*2097152, 512, FFC, 3, b1 + l*FFC, modb + l);
        ct_hgemm<1><<<dim3(DIMC/TBN, MM/64), 256, HG_SMEM1>>>(
            pfre, pfim, pwh + W2_OFF + (size_t)l*2097152, 2048, DIMC, 4, b2 + l*DIMC, nullptr);
    }
    ct_rmsnorm_f<<<MM, 128>>>(px, gfin, (float2*)d_out);
}